// round 9
// baseline (speedup 1.0000x reference)
#include <cuda_runtime.h>
#include <cstdint>

// LSTM CellForecaster: B=4096, T=512, H=128, IN=2, OUT=2, FUTURE=50
// 147 persistent CTAs x 512 threads, BB=28 batch rows/CTA (tail-guarded).
// Warp grid: Nb=4 (=SMSP) x Ng=2 gate-halves x Nk=2 k-halves.
// W_hh staged per gate-chunk via coalesced cp.async double-buffer (L2-resident).
// GEMM: packed fma.rn.f32x2 across K, rotate-in-place register pipelining.
// Epilogue split: kq0 owns gate rows gi=0, kq1 owns gi=1 -> both halves work.

#define HID    128
#define GATES  512
#define BB     28
#define NCTA   147
#define BTOT   4096
#define TENC   512
#define FUT    50
#define NSTEP  (TENC + FUT)
#define THREADS 512
#define WPITCH 132       // W chunk row pitch (floats), conflict-free LDS.128
#define TPITCH 132       // hT row pitch (floats)

struct alignas(16) SmemLayout {
    float W[2][128 * WPITCH];                 // double-buffered gate chunk
    float hT[BB * TPITCH];                    // h batch-major: hT[b][k]
    ulonglong2 pad_;                          // keep scr 16B aligned
    unsigned long long scr[2][2][2][4][7][32];// [parity][ownkq][gq][ty][p][tx]
    float bias[GATES];                        // b_ih + b_hh
    float wih[GATES * 2];
    float fcw[2 * HID];
    float fcb[2];
    float xin[BB * 2];                        // step input (x_t or fed-back y)
};

__device__ __forceinline__ uint32_t smem_u32(const void* p) {
    uint32_t a;
    asm("{ .reg .u64 t; cvta.to.shared.u64 t, %1; cvt.u32.u64 %0, t; }"
        : "=r"(a) : "l"(p));
    return a;
}
__device__ __forceinline__ void upk2(unsigned long long v, float& x, float& y) {
    asm("mov.b64 {%0,%1}, %2;" : "=f"(x), "=f"(y) : "l"(v));
}
__device__ __forceinline__ unsigned long long fma2(unsigned long long a,
                                                   unsigned long long b,
                                                   unsigned long long c) {
    unsigned long long d;
    asm("fma.rn.f32x2 %0, %1, %2, %3;" : "=l"(d) : "l"(a), "l"(b), "l"(c));
    return d;
}
__device__ __forceinline__ unsigned long long add2(unsigned long long a,
                                                   unsigned long long b) {
    unsigned long long d;
    asm("add.rn.f32x2 %0, %1, %2;" : "=l"(d) : "l"(a), "l"(b));
    return d;
}
__device__ __forceinline__ float sigf(float x) { return 1.f / (1.f + __expf(-x)); }
__device__ __forceinline__ float tanh_(float x) { return 2.f / (1.f + __expf(-2.f * x)) - 1.f; }

__device__ __forceinline__ void cpa16(uint32_t dst, const float* src) {
    asm volatile("cp.async.cg.shared.global [%0], [%1], 16;" :: "r"(dst), "l"(src));
}
#define CP_COMMIT() asm volatile("cp.async.commit_group;")
#define CP_WAIT0()  asm volatile("cp.async.wait_group 0;")

__global__ void __launch_bounds__(THREADS, 1)
lstm_forecast_kernel(const float* __restrict__ x,
                     const float* __restrict__ Wih,
                     const float* __restrict__ Whh,
                     const float* __restrict__ bih,
                     const float* __restrict__ bhh,
                     const float* __restrict__ fcw,
                     const float* __restrict__ fcb,
                     float* __restrict__ out)
{
    extern __shared__ char smraw[];
    SmemLayout& sm = *reinterpret_cast<SmemLayout*>(smraw);

    const int tid  = threadIdx.x;
    const int bat0 = blockIdx.x * BB;
    const int tx   = tid & 31;           // lane
    const int wrp  = tid >> 5;           // 0..15
    const int ty   = wrp & 3;            // batch group (7 rows) == SMSP
    const int gq   = (wrp >> 2) & 1;     // gate half (64 rows)
    const int kq   = wrp >> 3;           // k half (64 k-values)
    const int row0 = gq * 64 + tx;       // gate rows: row0 (gi0), row0+32 (gi1)
    const int bt0  = ty * 7;
    const int kb   = kq * 64;
    const int rh   = row0 + 32 * kq;     // OWNED hidden/gate row (epilogue)

    // ---- one-time init ----
    for (int i = tid; i < BB * TPITCH; i += THREADS) sm.hT[i] = 0.f;
    for (int g = tid; g < GATES; g += THREADS) {
        sm.bias[g]      = bih[g] + bhh[g];
        sm.wih[g*2 + 0] = Wih[g*2 + 0];
        sm.wih[g*2 + 1] = Wih[g*2 + 1];
    }
    for (int i = tid; i < 2 * HID; i += THREADS) sm.fcw[i] = fcw[i];
    if (tid < 2) sm.fcb[tid] = fcb[tid];

    const uint32_t wbase0 = smem_u32(&sm.W[0][0]);
    const uint32_t wbase1 = smem_u32(&sm.W[1][0]);

    auto stage = [&](int chunk, int buf) {
        const float*  src = Whh + chunk * (128 * HID);
        const uint32_t wb = buf ? wbase1 : wbase0;
        #pragma unroll
        for (int r = 0; r < 8; r++) {
            int e    = tid + THREADS * r;         // 0..4095 float4 slots
            int wrow = e >> 5;
            int c4   = (e & 31) << 2;
            cpa16(wb + (uint32_t)(wrow * WPITCH + c4) * 4u, src + wrow * HID + c4);
        }
        CP_COMMIT();
    };

    stage(0, 0);

    // owned state: 1 gate/hidden row (rh) x 7 batch
    float creg[7], ti[7];
    #pragma unroll
    for (int p = 0; p < 7; p++) { creg[p] = 0.f; ti[p] = 0.f; }

    __syncthreads();

    for (int s = 0; s < NSTEP; s++) {
        // ---- step input: x_t (encode) or y = h@fc_w^T + fc_b (forecast) ----
        if (tid < 2 * BB) {
            const int b  = tid >> 1;
            const int io = tid & 1;
            const int bg = bat0 + b;
            const bool ok = bg < BTOT;
            if (s < TENC) {
                sm.xin[b * 2 + io] = ok ? x[(size_t)bg * (TENC * 2) + s * 2 + io] : 0.f;
            } else {
                float acc = sm.fcb[io];
                const float* fr = &sm.fcw[io * HID];
                const float* hr = &sm.hT[b * TPITCH];
                #pragma unroll 8
                for (int k = 0; k < HID; k += 4) {
                    float4 hq = *reinterpret_cast<const float4*>(&hr[k]);
                    float4 fq = *reinterpret_cast<const float4*>(&fr[k]);
                    acc += hq.x*fq.x + hq.y*fq.y + hq.z*fq.z + hq.w*fq.w;
                }
                sm.xin[b * 2 + io] = ok ? acc : 0.f;
                if (ok) out[(size_t)bg * (FUT * 2) + (s - TENC) * 2 + io] = acc;
            }
        }
        __syncthreads();   // xin visible

        #pragma unroll 1
        for (int ch = 0; ch < 4; ch++) {
            CP_WAIT0();
            __syncthreads();                 // W[ch] visible CTA-wide
            if (!(s == NSTEP - 1 && ch == 3))
                stage((ch + 1) & 3, (ch + 1) & 1);

            // ---- partial GEMM over this warp's k-half ----
            unsigned long long acc0[7], acc1[7];
            #pragma unroll
            for (int p = 0; p < 7; p++) { acc0[p] = 0ull; acc1[p] = 0ull; }

            const float* Wb  = &sm.W[ch & 1][0];
            const float* Wr0 = &Wb[row0 * WPITCH];
            const float* Wr1 = &Wb[(row0 + 32) * WPITCH];

            // rotate-in-place pipeline: load for iter+1 right after consuming
            ulonglong2 wv0 = *reinterpret_cast<const ulonglong2*>(Wr0 + kb);
            ulonglong2 wv1 = *reinterpret_cast<const ulonglong2*>(Wr1 + kb);
            ulonglong2 hv[7];
            #pragma unroll
            for (int p = 0; p < 7; p++)
                hv[p] = *reinterpret_cast<const ulonglong2*>(&sm.hT[(bt0 + p) * TPITCH + kb]);

            #pragma unroll
            for (int it = 0; it < 16; it++) {
                const int knxt = kb + 4 * ((it + 1) & 15);   // wrap: harmless
                ulonglong2 w0 = wv0, w1 = wv1;
                wv0 = *reinterpret_cast<const ulonglong2*>(Wr0 + knxt);
                wv1 = *reinterpret_cast<const ulonglong2*>(Wr1 + knxt);
                #pragma unroll
                for (int p = 0; p < 7; p++) {
                    ulonglong2 h = hv[p];
                    hv[p] = *reinterpret_cast<const ulonglong2*>(&sm.hT[(bt0 + p) * TPITCH + knxt]);
                    acc0[p] = fma2(w0.x, h.x, acc0[p]);
                    acc0[p] = fma2(w0.y, h.y, acc0[p]);
                    acc1[p] = fma2(w1.x, h.x, acc1[p]);
                    acc1[p] = fma2(w1.y, h.y, acc1[p]);
                }
            }

            // ---- exchange non-owned gi partial ----
            // kq0 owns gi0 (writes acc1 for owner kq1); kq1 owns gi1 (writes acc0).
            {
                unsigned long long (*dst)[32] = sm.scr[ch & 1][kq ^ 1][gq][ty];
                #pragma unroll
                for (int p = 0; p < 7; p++)
                    dst[p][tx] = kq ? acc0[p] : acc1[p];
            }
            __syncthreads();   // partials visible; all hT/W reads for ch done

            // ---- combine + bias + x@W_ih^T + pointwise on OWNED row rh ----
            {
                unsigned long long (*src)[32] = sm.scr[ch & 1][kq][gq][ty];
                const int G   = ch * 128 + rh;
                const float bsv = sm.bias[G];
                const float w0 = sm.wih[G * 2], w1 = sm.wih[G * 2 + 1];
                #pragma unroll
                for (int p = 0; p < 7; p++) {
                    unsigned long long own = kq ? acc1[p] : acc0[p];
                    unsigned long long tot = add2(own, src[p][tx]);
                    float va, vb;
                    upk2(tot, va, vb);
                    const int b = bt0 + p;
                    float gate = va + vb + bsv + sm.xin[b*2]*w0 + sm.xin[b*2+1]*w1;
                    if (ch == 0) {                         // i
                        ti[p] = sigf(gate);
                    } else if (ch == 1) {                  // f
                        creg[p] *= sigf(gate);
                    } else if (ch == 2) {                  // g
                        creg[p] += ti[p] * tanh_(gate);
                    } else {                               // o: hT dead now
                        sm.hT[b * TPITCH + rh] = sigf(gate) * tanh_(creg[p]);
                    }
                }
            }
        }
        __syncthreads();   // new hT visible for fc-head / next step
    }
}

extern "C" void kernel_launch(void* const* d_in, const int* in_sizes, int n_in,
                              void* d_out, int out_size) {
    const float* x    = (const float*)d_in[0];
    const float* Wih  = (const float*)d_in[1];
    const float* Whh  = (const float*)d_in[2];
    const float* bih  = (const float*)d_in[3];
    const float* bhh  = (const float*)d_in[4];
    const float* fcw  = (const float*)d_in[5];
    const float* fcb  = (const float*)d_in[6];
    float* out = (float*)d_out;

    const int smem_bytes = (int)sizeof(SmemLayout);
    cudaFuncSetAttribute(lstm_forecast_kernel,
                         cudaFuncAttributeMaxDynamicSharedMemorySize, smem_bytes);

    lstm_forecast_kernel<<<NCTA, THREADS, smem_bytes>>>(
        x, Wih, Whh, bih, bhh, fcw, fcb, out);
}

// round 11
// speedup vs baseline: 1.0833x; 1.0833x over previous
#include <cuda_runtime.h>
#include <cstdint>

// LSTM CellForecaster: B=4096, T=512, H=128, IN=2, OUT=2, FUTURE=50
// 147 persistent CTAs x 512 threads, BB=28 batch rows/CTA (tail-guarded).
// Warp grid: Nb=4 (=SMSP) x Ng=2 gate-halves x Nk=2 k-halves.
// W_hh pre-transposed ONCE into lane-major layout (g_Wt) so the mainloop
// streams W directly from L2 via coalesced LDG.128 (nL=4) with depth-2
// register prefetch. No smem W, no cp.async, 6 syncs/step.
// R11 FIX vs R10: chunk stride in g_Wt is 16384 floats (ch is the SLOWEST
// axis: ch->16384, gq->8192, kq->4096, it->256, pair->128, tx->4). R10
// used ch*4096, reading wrong W rows for chunks 1-3.

#define HID    128
#define GATES  512
#define BB     28
#define NCTA   147
#define BTOT   4096
#define TENC   512
#define FUT    50
#define NSTEP  (TENC + FUT)
#define THREADS 512
#define TPITCH 132       // hT row pitch (floats)

// Transposed W_hh: idx = ((((ch*2+gq)*2+kq)*16 + it)*2 + pair)*32 + tx, 4 floats each.
__device__ float g_Wt[GATES * HID];   // 256 KB

struct alignas(16) SmemLayout {
    float hT[BB * TPITCH];                    // h batch-major: hT[b][k]
    unsigned long long scr[2][2][2][4][7][32];// [parity][ownkq][gq][ty][p][tx]
    float bias[GATES];                        // b_ih + b_hh
    float wih[GATES * 2];
    float fcw[2 * HID];
    float fcb[2];
    float xin[BB * 2];                        // step input (x_t or fed-back y)
};

__device__ __forceinline__ void upk2(unsigned long long v, float& x, float& y) {
    asm("mov.b64 {%0,%1}, %2;" : "=f"(x), "=f"(y) : "l"(v));
}
__device__ __forceinline__ unsigned long long fma2(unsigned long long a,
                                                   unsigned long long b,
                                                   unsigned long long c) {
    unsigned long long d;
    asm("fma.rn.f32x2 %0, %1, %2, %3;" : "=l"(d) : "l"(a), "l"(b), "l"(c));
    return d;
}
__device__ __forceinline__ unsigned long long add2(unsigned long long a,
                                                   unsigned long long b) {
    unsigned long long d;
    asm("add.rn.f32x2 %0, %1, %2;" : "=l"(d) : "l"(a), "l"(b));
    return d;
}
__device__ __forceinline__ float sigf(float x) { return 1.f / (1.f + __expf(-x)); }
__device__ __forceinline__ float tanh_(float x) { return 2.f / (1.f + __expf(-2.f * x)) - 1.f; }

// ---- prologue: permute W_hh into lane-major streaming layout ----
__global__ void transpose_whh_kernel(const float* __restrict__ Whh) {
    int idx = blockIdx.x * blockDim.x + threadIdx.x;   // 16384 float4 groups
    if (idx < GATES * HID / 4) {
        int tx   = idx & 31;
        int pair = (idx >> 5) & 1;
        int it   = (idx >> 6) & 15;
        int kq   = (idx >> 10) & 1;
        int gq   = (idx >> 11) & 1;
        int ch   = (idx >> 12) & 3;
        int row  = ch * 128 + gq * 64 + pair * 32 + tx;
        int k    = kq * 64 + it * 4;
        float4 v = *reinterpret_cast<const float4*>(Whh + row * HID + k);
        *reinterpret_cast<float4*>(g_Wt + (size_t)idx * 4) = v;
    }
}

__global__ void __launch_bounds__(THREADS, 1)
lstm_forecast_kernel(const float* __restrict__ x,
                     const float* __restrict__ Wih,
                     const float* __restrict__ bih,
                     const float* __restrict__ bhh,
                     const float* __restrict__ fcw,
                     const float* __restrict__ fcb,
                     float* __restrict__ out)
{
    extern __shared__ char smraw[];
    SmemLayout& sm = *reinterpret_cast<SmemLayout*>(smraw);

    const int tid  = threadIdx.x;
    const int bat0 = blockIdx.x * BB;
    const int tx   = tid & 31;           // lane
    const int wrp  = tid >> 5;           // 0..15
    const int ty   = wrp & 3;            // batch group (7 rows) == SMSP
    const int gq   = (wrp >> 2) & 1;     // gate half (64 rows)
    const int kq   = wrp >> 3;           // k half (64 k-values)
    const int row0 = gq * 64 + tx;       // gate rows: row0 (gi0), row0+32 (gi1)
    const int bt0  = ty * 7;
    const int kb   = kq * 64;
    const int rh   = row0 + 32 * kq;     // OWNED hidden/gate row (epilogue)

    // per-(gq,kq) W stream base within a chunk block
    const float* wbase = g_Wt + (size_t)(gq * 2 + kq) * 4096 + tx * 4;

    // ---- one-time init ----
    for (int i = tid; i < BB * TPITCH; i += THREADS) sm.hT[i] = 0.f;
    for (int g = tid; g < GATES; g += THREADS) {
        sm.bias[g]      = bih[g] + bhh[g];
        sm.wih[g*2 + 0] = Wih[g*2 + 0];
        sm.wih[g*2 + 1] = Wih[g*2 + 1];
    }
    for (int i = tid; i < 2 * HID; i += THREADS) sm.fcw[i] = fcw[i];
    if (tid < 2) sm.fcb[tid] = fcb[tid];

    // owned state: 1 gate/hidden row (rh) x 7 batch
    float creg[7], ti[7];
    #pragma unroll
    for (int p = 0; p < 7; p++) { creg[p] = 0.f; ti[p] = 0.f; }

    __syncthreads();

    for (int s = 0; s < NSTEP; s++) {
        // ---- step input: x_t (encode) or y = h@fc_w^T + fc_b (forecast) ----
        if (tid < 2 * BB) {
            const int b  = tid >> 1;
            const int io = tid & 1;
            const int bg = bat0 + b;
            const bool ok = bg < BTOT;
            if (s < TENC) {
                sm.xin[b * 2 + io] = ok ? x[(size_t)bg * (TENC * 2) + s * 2 + io] : 0.f;
            } else {
                float acc = sm.fcb[io];
                const float* fr = &sm.fcw[io * HID];
                const float* hr = &sm.hT[b * TPITCH];
                #pragma unroll 8
                for (int k = 0; k < HID; k += 4) {
                    float4 hq = *reinterpret_cast<const float4*>(&hr[k]);
                    float4 fq = *reinterpret_cast<const float4*>(&fr[k]);
                    acc += hq.x*fq.x + hq.y*fq.y + hq.z*fq.z + hq.w*fq.w;
                }
                sm.xin[b * 2 + io] = ok ? acc : 0.f;
                if (ok) out[(size_t)bg * (FUT * 2) + (s - TENC) * 2 + io] = acc;
            }
        }
        __syncthreads();   // xin visible (hT stable from end-of-step sync)

        #pragma unroll 1
        for (int ch = 0; ch < 4; ch++) {
            // ---- partial GEMM over this warp's k-half; W streamed from L2 ----
            unsigned long long acc0[7], acc1[7];
            #pragma unroll
            for (int p = 0; p < 7; p++) { acc0[p] = 0ull; acc1[p] = 0ull; }

            // FIX: ch (slowest axis) stride is 4*4096 = 16384 floats
            const float* wp = wbase + (size_t)ch * 16384;  // [it][pair][tx][4]

            // depth-2 W prefetch (LDG.128, 512B/warp contiguous)
            ulonglong2 wa0 = *reinterpret_cast<const ulonglong2*>(wp);
            ulonglong2 wa1 = *reinterpret_cast<const ulonglong2*>(wp + 128);
            ulonglong2 wb0 = *reinterpret_cast<const ulonglong2*>(wp + 256);
            ulonglong2 wb1 = *reinterpret_cast<const ulonglong2*>(wp + 384);

            // h operands: rotate-in-place LDS pipeline
            ulonglong2 hv[7];
            #pragma unroll
            for (int p = 0; p < 7; p++)
                hv[p] = *reinterpret_cast<const ulonglong2*>(&sm.hT[(bt0 + p) * TPITCH + kb]);

            #pragma unroll
            for (int it = 0; it < 16; it++) {
                const int knxt = kb + 4 * ((it + 1) & 15);   // wrap: harmless
                ulonglong2 w0 = wa0, w1 = wa1;
                wa0 = wb0; wa1 = wb1;
                if (it + 2 < 16) {
                    const float* wn = wp + (size_t)(it + 2) * 256;
                    wb0 = *reinterpret_cast<const ulonglong2*>(wn);
                    wb1 = *reinterpret_cast<const ulonglong2*>(wn + 128);
                }
                #pragma unroll
                for (int p = 0; p < 7; p++) {
                    ulonglong2 h = hv[p];
                    hv[p] = *reinterpret_cast<const ulonglong2*>(&sm.hT[(bt0 + p) * TPITCH + knxt]);
                    acc0[p] = fma2(w0.x, h.x, acc0[p]);
                    acc0[p] = fma2(w0.y, h.y, acc0[p]);
                    acc1[p] = fma2(w1.x, h.x, acc1[p]);
                    acc1[p] = fma2(w1.y, h.y, acc1[p]);
                }
            }

            // ---- exchange non-owned gi partial ----
            // kq0 owns gi0 (writes acc1 for owner kq1); kq1 owns gi1 (writes acc0).
            {
                unsigned long long (*dst)[32] = sm.scr[ch & 1][kq ^ 1][gq][ty];
                #pragma unroll
                for (int p = 0; p < 7; p++)
                    dst[p][tx] = kq ? acc0[p] : acc1[p];
            }
            __syncthreads();   // partials visible; all hT reads for ch done

            // ---- combine + bias + x@W_ih^T + pointwise on OWNED row rh ----
            {
                unsigned long long (*src)[32] = sm.scr[ch & 1][kq][gq][ty];
                const int G   = ch * 128 + rh;
                const float bsv = sm.bias[G];
                const float w0 = sm.wih[G * 2], w1 = sm.wih[G * 2 + 1];
                #pragma unroll
                for (int p = 0; p < 7; p++) {
                    unsigned long long own = kq ? acc1[p] : acc0[p];
                    unsigned long long tot = add2(own, src[p][tx]);
                    float va, vb;
                    upk2(tot, va, vb);
                    const int b = bt0 + p;
                    float gate = va + vb + bsv + sm.xin[b*2]*w0 + sm.xin[b*2+1]*w1;
                    if (ch == 0) {                         // i
                        ti[p] = sigf(gate);
                    } else if (ch == 1) {                  // f
                        creg[p] *= sigf(gate);
                    } else if (ch == 2) {                  // g
                        creg[p] += ti[p] * tanh_(gate);
                    } else {                               // o: hT dead now
                        sm.hT[b * TPITCH + rh] = sigf(gate) * tanh_(creg[p]);
                    }
                }
            }
        }
        __syncthreads();   // new hT visible for fc-head / next step
    }
}

extern "C" void kernel_launch(void* const* d_in, const int* in_sizes, int n_in,
                              void* d_out, int out_size) {
    const float* x    = (const float*)d_in[0];
    const float* Wih  = (const float*)d_in[1];
    const float* Whh  = (const float*)d_in[2];
    const float* bih  = (const float*)d_in[3];
    const float* bhh  = (const float*)d_in[4];
    const float* fcw  = (const float*)d_in[5];
    const float* fcb  = (const float*)d_in[6];
    float* out = (float*)d_out;

    transpose_whh_kernel<<<(GATES * HID / 4 + 255) / 256, 256>>>(Whh);

    const int smem_bytes = (int)sizeof(SmemLayout);
    cudaFuncSetAttribute(lstm_forecast_kernel,
                         cudaFuncAttributeMaxDynamicSharedMemorySize, smem_bytes);

    lstm_forecast_kernel<<<NCTA, THREADS, smem_bytes>>>(
        x, Wih, bih, bhh, fcw, fcb, out);
}